// round 1
// baseline (speedup 1.0000x reference)
#include <cuda_runtime.h>
#include <math.h>

// Problem constants
#define BB 16
#define LL 512
#define NJ 4      // HEAD_IN
#define NO 4      // HEAD_OUT
#define DD 64     // DIM
#define SCALE 0.125f   // 1/sqrt(64)

// Tiling
#define LT 64          // l rows per block
#define MT 128         // m chunk
#define NCH (LL/MT)    // 4
#define THREADS 256

// Shared strides (in floats) chosen to avoid bank conflicts + keep 16B alignment
#define SPAD 516       // scores row stride (512 + 4)
#define XS 68          // [rows][D] tiles
#define TS 132         // transposed [D][MT] tile row stride

#define OUT_ELEMS (BB*LL*NO*DD)   // 2097152; attn follows at this offset

// smem layout (floats):
//   sS  : LT*SPAD            = 33024
//   buf : max(128*68,64*132) =  8704   (phase A: sW[0..4351] + sXl[4352..8703])
//   sQ  : 64*68              =  4352
#define SMEM_FLOATS (LT*SPAD + 8704 + 4352)   // 46080 floats = 184320 B

__global__ __launch_bounds__(THREADS, 1)
void convattn_kernel(const float* __restrict__ inp,
                     const float* __restrict__ W,
                     float* __restrict__ out)
{
    extern __shared__ float sm[];
    float* sS  = sm;                  // scores / attn probs
    float* buf = sm + LT * SPAD;      // x chunk (normal or transposed) / W+xl
    float* sQ  = buf + 8704;          // q tile (pre-scaled)
    float* sW  = buf;                 // phase A alias
    float* sXl = buf + 4352;          // phase A alias

    const int tid   = threadIdx.x;
    const int ltile = blockIdx.x;     // 0..7
    const int b     = blockIdx.y;     // 0..15
    const int o     = blockIdx.z;     // 0..3
    const int l0g   = ltile * LT;

    const int tx = tid & 15;          // 0..15
    const int ty = tid >> 4;          // 0..15
    const int warp = tid >> 5;        // 0..7
    const int lane = tid & 31;

    float* attn_out = out + OUT_ELEMS;

    // persistent ctx accumulator (summed over j), thread tile 4(l) x 4(d)
    float cacc[4][4];
    #pragma unroll
    for (int i = 0; i < 4; i++)
        #pragma unroll
        for (int jj = 0; jj < 4; jj++) cacc[i][jj] = 0.f;

    for (int j = 0; j < NJ; ++j) {
        // ---------------- Phase A: load W[o][j], x_l tile; compute q ----------------
        {
            const float* Wp = W + ((o * NJ + j) * DD) * DD;
            #pragma unroll
            for (int t = 0; t < 4; t++) {
                int idx = tid + t * THREADS;          // float4 index, 1024 total
                int r   = idx >> 4;
                int c4  = idx & 15;
                float4 v = *(const float4*)(Wp + r * DD + c4 * 4);
                *(float4*)(sW + r * XS + c4 * 4) = v;
            }
            #pragma unroll
            for (int t = 0; t < 4; t++) {
                int idx = tid + t * THREADS;
                int r   = idx >> 4;                   // local l
                int c4  = idx & 15;
                float4 v = *(const float4*)(inp + (((b * LL + l0g + r) * NJ + j) * DD) + c4 * 4);
                *(float4*)(sXl + r * XS + c4 * 4) = v;
            }
        }
        __syncthreads();
        {
            // q[l][e] = sum_d xl[l][d]*W[d][e], microtile 4x4
            float acc[4][4];
            #pragma unroll
            for (int i = 0; i < 4; i++)
                #pragma unroll
                for (int jj = 0; jj < 4; jj++) acc[i][jj] = 0.f;
            const int l0 = ty * 4, e0 = tx * 4;
            #pragma unroll 8
            for (int k = 0; k < DD; k++) {
                float a0 = sXl[(l0 + 0) * XS + k];
                float a1 = sXl[(l0 + 1) * XS + k];
                float a2 = sXl[(l0 + 2) * XS + k];
                float a3 = sXl[(l0 + 3) * XS + k];
                float4 w4 = *(float4*)(sW + k * XS + e0);
                acc[0][0] += a0 * w4.x; acc[0][1] += a0 * w4.y; acc[0][2] += a0 * w4.z; acc[0][3] += a0 * w4.w;
                acc[1][0] += a1 * w4.x; acc[1][1] += a1 * w4.y; acc[1][2] += a1 * w4.z; acc[1][3] += a1 * w4.w;
                acc[2][0] += a2 * w4.x; acc[2][1] += a2 * w4.y; acc[2][2] += a2 * w4.z; acc[2][3] += a2 * w4.w;
                acc[3][0] += a3 * w4.x; acc[3][1] += a3 * w4.y; acc[3][2] += a3 * w4.z; acc[3][3] += a3 * w4.w;
            }
            #pragma unroll
            for (int i = 0; i < 4; i++) {
                float4 v = make_float4(acc[i][0] * SCALE, acc[i][1] * SCALE,
                                       acc[i][2] * SCALE, acc[i][3] * SCALE);
                *(float4*)(sQ + (l0 + i) * XS + e0) = v;
            }
        }
        __syncthreads();

        // ---------------- Phase B: scores S[l][m] = q . x_m, chunked over m ----------------
        for (int c = 0; c < NCH; c++) {
            // load x chunk transposed: buf[d][m], stride TS
            #pragma unroll
            for (int t = 0; t < 8; t++) {
                int idx = tid + t * THREADS;          // 2048 float4
                int m   = idx >> 4;
                int d4  = idx & 15;
                float4 v = *(const float4*)(inp + (((b * LL + c * MT + m) * NJ + j) * DD) + d4 * 4);
                buf[(d4 * 4 + 0) * TS + m] = v.x;
                buf[(d4 * 4 + 1) * TS + m] = v.y;
                buf[(d4 * 4 + 2) * TS + m] = v.z;
                buf[(d4 * 4 + 3) * TS + m] = v.w;
            }
            __syncthreads();

            float acc[4][8];
            #pragma unroll
            for (int i = 0; i < 4; i++)
                #pragma unroll
                for (int jj = 0; jj < 8; jj++) acc[i][jj] = 0.f;
            const int l0 = ty * 4, m0 = tx * 8;
            #pragma unroll 4
            for (int k = 0; k < DD; k++) {
                float a0 = sQ[(l0 + 0) * XS + k];
                float a1 = sQ[(l0 + 1) * XS + k];
                float a2 = sQ[(l0 + 2) * XS + k];
                float a3 = sQ[(l0 + 3) * XS + k];
                float4 b0 = *(float4*)(buf + k * TS + m0);
                float4 b1 = *(float4*)(buf + k * TS + m0 + 4);
                float bv[8] = {b0.x, b0.y, b0.z, b0.w, b1.x, b1.y, b1.z, b1.w};
                #pragma unroll
                for (int jj = 0; jj < 8; jj++) {
                    acc[0][jj] += a0 * bv[jj];
                    acc[1][jj] += a1 * bv[jj];
                    acc[2][jj] += a2 * bv[jj];
                    acc[3][jj] += a3 * bv[jj];
                }
            }
            #pragma unroll
            for (int i = 0; i < 4; i++) {
                float4 v0 = make_float4(acc[i][0], acc[i][1], acc[i][2], acc[i][3]);
                float4 v1 = make_float4(acc[i][4], acc[i][5], acc[i][6], acc[i][7]);
                *(float4*)(sS + (l0 + i) * SPAD + c * MT + m0)     = v0;
                *(float4*)(sS + (l0 + i) * SPAD + c * MT + m0 + 4) = v1;
            }
            __syncthreads();
        }

        // ---------------- Phase C: softmax per row + write attn ----------------
        {
            #pragma unroll 1
            for (int r = 0; r < 8; r++) {
                const int l = warp * 8 + r;
                float* row = sS + l * SPAD;
                // max
                float mx = -1e30f;
                #pragma unroll
                for (int t = 0; t < 16; t++) mx = fmaxf(mx, row[lane + t * 32]);
                #pragma unroll
                for (int s = 16; s > 0; s >>= 1) mx = fmaxf(mx, __shfl_xor_sync(0xffffffffu, mx, s));
                // exp + sum (store exp back)
                float sum = 0.f;
                #pragma unroll
                for (int t = 0; t < 16; t++) {
                    float e = __expf(row[lane + t * 32] - mx);
                    row[lane + t * 32] = e;
                    sum += e;
                }
                #pragma unroll
                for (int s = 16; s > 0; s >>= 1) sum += __shfl_xor_sync(0xffffffffu, sum, s);
                float inv = 1.f / sum;
                __syncwarp();
                // normalize in smem + coalesced gmem write
                long aoff = ((long)(((o * NJ + j) * BB + b) * LL + l0g + l)) * LL;
                float* ap = attn_out + aoff;
                #pragma unroll
                for (int t = 0; t < 4; t++) {
                    float4 v = *(float4*)(row + lane * 4 + t * 128);
                    v.x *= inv; v.y *= inv; v.z *= inv; v.w *= inv;
                    *(float4*)(row + lane * 4 + t * 128) = v;
                    *(float4*)(ap + lane * 4 + t * 128)  = v;
                }
            }
        }
        __syncthreads();

        // ---------------- Phase D: ctx += P @ x, chunked over m ----------------
        for (int c = 0; c < NCH; c++) {
            // load x chunk normal: buf[m][d], stride XS
            #pragma unroll
            for (int t = 0; t < 8; t++) {
                int idx = tid + t * THREADS;
                int m   = idx >> 4;
                int d4  = idx & 15;
                float4 v = *(const float4*)(inp + (((b * LL + c * MT + m) * NJ + j) * DD) + d4 * 4);
                *(float4*)(buf + m * XS + d4 * 4) = v;
            }
            __syncthreads();

            const int l0 = ty * 4, d0 = tx * 4;
            #pragma unroll 4
            for (int k = 0; k < MT; k++) {
                float p0 = sS[(l0 + 0) * SPAD + c * MT + k];
                float p1 = sS[(l0 + 1) * SPAD + c * MT + k];
                float p2 = sS[(l0 + 2) * SPAD + c * MT + k];
                float p3 = sS[(l0 + 3) * SPAD + c * MT + k];
                float4 xv = *(float4*)(buf + k * XS + d0);
                cacc[0][0] += p0 * xv.x; cacc[0][1] += p0 * xv.y; cacc[0][2] += p0 * xv.z; cacc[0][3] += p0 * xv.w;
                cacc[1][0] += p1 * xv.x; cacc[1][1] += p1 * xv.y; cacc[1][2] += p1 * xv.z; cacc[1][3] += p1 * xv.w;
                cacc[2][0] += p2 * xv.x; cacc[2][1] += p2 * xv.y; cacc[2][2] += p2 * xv.z; cacc[2][3] += p2 * xv.w;
                cacc[3][0] += p3 * xv.x; cacc[3][1] += p3 * xv.y; cacc[3][2] += p3 * xv.z; cacc[3][3] += p3 * xv.w;
            }
            __syncthreads();
        }
    } // j loop

    // ---------------- write out = mean_j ctx, layout [b, l, o, d] ----------------
    {
        const int l0 = ty * 4, d0 = tx * 4;
        #pragma unroll
        for (int i = 0; i < 4; i++) {
            float4 v = make_float4(cacc[i][0] * 0.25f, cacc[i][1] * 0.25f,
                                   cacc[i][2] * 0.25f, cacc[i][3] * 0.25f);
            *(float4*)(out + ((b * LL + l0g + l0 + i) * NO + o) * DD + d0) = v;
        }
    }
}

extern "C" void kernel_launch(void* const* d_in, const int* in_sizes, int n_in,
                              void* d_out, int out_size) {
    const float* inp = (const float*)d_in[0];   // [16,512,4,64]
    const float* W   = (const float*)d_in[1];   // [4,4,64,64]
    float* out = (float*)d_out;                 // out (2097152) then attn (67108864)

    static int smem_set = 0;
    const int smem_bytes = SMEM_FLOATS * sizeof(float);  // 184320
    if (!smem_set) {
        cudaFuncSetAttribute(convattn_kernel,
                             cudaFuncAttributeMaxDynamicSharedMemorySize, smem_bytes);
        smem_set = 1;
    }

    dim3 grid(LL / LT, BB, NO);   // (8, 16, 4)
    convattn_kernel<<<grid, THREADS, smem_bytes>>>(inp, W, out);
}

// round 3
// speedup vs baseline: 2.8384x; 2.8384x over previous
#include <cuda_runtime.h>
#include <cuda_bf16.h>
#include <stdint.h>
#include <cstdint>
#include <math.h>

// Problem constants
#define BB 16
#define LL 512
#define NJ 4
#define NO 4
#define DD 64
#define SCALE 0.125f

#define LT 64          // l rows per block
#define THREADS 256
#define SPAD 520       // fp32 scores row stride
#define XP 72          // bf16 tile row stride (144B, conflict-free for ldmatrix)

#define OUT_ELEMS (BB*LL*NO*DD)   // 2097152; attn follows

// smem: sS fp32 64x520 = 133120B; xh/xl 128x72 bf16 = 18432B each;
//       qh/ql 64x72 bf16 = 9216B each. total = 188416B
#define SMEM_BYTES (LT*SPAD*4 + (128*XP)*2*2 + (64*XP)*2*2)

__device__ __forceinline__ uint32_t s2u(const void* p) {
    return (uint32_t)__cvta_generic_to_shared(p);
}
__device__ __forceinline__ void ldm_x4(uint32_t a, uint32_t& r0, uint32_t& r1,
                                       uint32_t& r2, uint32_t& r3) {
    asm volatile("ldmatrix.sync.aligned.m8n8.x4.shared.b16 {%0,%1,%2,%3}, [%4];"
                 : "=r"(r0), "=r"(r1), "=r"(r2), "=r"(r3) : "r"(a));
}
__device__ __forceinline__ void ldm_x4t(uint32_t a, uint32_t& r0, uint32_t& r1,
                                        uint32_t& r2, uint32_t& r3) {
    asm volatile("ldmatrix.sync.aligned.m8n8.x4.trans.shared.b16 {%0,%1,%2,%3}, [%4];"
                 : "=r"(r0), "=r"(r1), "=r"(r2), "=r"(r3) : "r"(a));
}
__device__ __forceinline__ void mma_bf16(float* c, uint32_t a0, uint32_t a1,
                                         uint32_t a2, uint32_t a3,
                                         uint32_t b0, uint32_t b1) {
    asm volatile("mma.sync.aligned.m16n8k16.row.col.f32.bf16.bf16.f32 "
                 "{%0,%1,%2,%3},{%4,%5,%6,%7},{%8,%9},{%0,%1,%2,%3};"
                 : "+f"(c[0]), "+f"(c[1]), "+f"(c[2]), "+f"(c[3])
                 : "r"(a0), "r"(a1), "r"(a2), "r"(a3), "r"(b0), "r"(b1));
}
__device__ __forceinline__ uint32_t pack2(float x0, float x1) {
    __nv_bfloat162 v = __floats2bfloat162_rn(x0, x1);
    return *reinterpret_cast<uint32_t*>(&v);
}
// hi/lo split of a pair, packed as bf16x2
__device__ __forceinline__ void split2(float x0, float x1, uint32_t& h, uint32_t& l) {
    float h0 = __bfloat162float(__float2bfloat16_rn(x0));
    float h1 = __bfloat162float(__float2bfloat16_rn(x1));
    h = pack2(x0, x1);
    l = pack2(x0 - h0, x1 - h1);
}
// convert float4 -> hi/lo bf16, store 8B each
__device__ __forceinline__ void split_store4(__nv_bfloat16* hb, __nv_bfloat16* lb,
                                             int off, float4 v) {
    float h0 = __bfloat162float(__float2bfloat16_rn(v.x));
    float h1 = __bfloat162float(__float2bfloat16_rn(v.y));
    float h2 = __bfloat162float(__float2bfloat16_rn(v.z));
    float h3 = __bfloat162float(__float2bfloat16_rn(v.w));
    uint2 H = make_uint2(pack2(v.x, v.y), pack2(v.z, v.w));
    uint2 L = make_uint2(pack2(v.x - h0, v.y - h1), pack2(v.z - h2, v.w - h3));
    *(uint2*)(hb + off) = H;
    *(uint2*)(lb + off) = L;
}

__global__ __launch_bounds__(THREADS, 1)
void convattn_mma_kernel(const float* __restrict__ inp,
                         const float* __restrict__ W,
                         float* __restrict__ out)
{
    extern __shared__ char smem[];
    float* sS = (float*)smem;
    __nv_bfloat16* xh_s = (__nv_bfloat16*)(smem + LT * SPAD * 4);
    __nv_bfloat16* xl_s = xh_s + 128 * XP;
    __nv_bfloat16* qh_s = xl_s + 128 * XP;
    __nv_bfloat16* ql_s = qh_s + 64 * XP;
    const uint32_t xh_u = s2u(xh_s), xl_u = s2u(xl_s);
    const uint32_t qh_u = s2u(qh_s), ql_u = s2u(ql_s);

    const int tid  = threadIdx.x;
    const int warp = tid >> 5;
    const int lane = tid & 31;
    const int g = lane >> 2, t = lane & 3;          // quad row / quad col
    const int lr = lane & 15, lc = (lane >> 4) * 8; // ldmatrix addressing

    const int l0g = blockIdx.x * LT;   // 0..7 tiles
    const int b   = blockIdx.y;
    const int o   = blockIdx.z;

    const int mw = warp & 3;           // m-tile (16 rows) within l-tile
    const int nh = warp >> 2;          // n-half selector
    const int lm0 = mw * 16;

    float* attn_out = out + OUT_ELEMS;

    // ctx accumulator: 4 d-tiles x 4 regs, persists across j
    float ctx[4][4];
    #pragma unroll
    for (int q = 0; q < 4; q++)
        #pragma unroll
        for (int i = 0; i < 4; i++) ctx[q][i] = 0.f;

    for (int j = 0; j < NJ; ++j) {
        // ============ Phase A: stage xl-tile + W as bf16 hi/lo; q = xl@W ============
        {
            const float* xlg = inp + ((size_t)(b * LL + l0g) * NJ + j) * DD;
            #pragma unroll
            for (int it = 0; it < 4; it++) {
                int idx = tid + it * THREADS;            // 1024 float4
                int r = idx >> 4, c4 = (idx & 15) * 4;
                float4 v = *(const float4*)(xlg + r * (NJ * DD) + c4);
                split_store4(xh_s, xl_s, r * XP + c4, v);      // rows 0..63: xl tile
            }
            const float* Wp = W + (size_t)(o * NJ + j) * DD * DD;
            #pragma unroll
            for (int it = 0; it < 4; it++) {
                int idx = tid + it * THREADS;
                int r = idx >> 4, c4 = (idx & 15) * 4;
                float4 v = *(const float4*)(Wp + r * DD + c4);
                split_store4(xh_s, xl_s, (64 + r) * XP + c4, v); // rows 64..127: W [d][e]
            }
        }
        __syncthreads();
        {
            float qacc[4][4];
            #pragma unroll
            for (int q = 0; q < 4; q++)
                #pragma unroll
                for (int i = 0; i < 4; i++) qacc[q][i] = 0.f;
            #pragma unroll
            for (int ks = 0; ks < 4; ks++) {
                int k0 = ks * 16;
                uint32_t ah[4], al[4];
                uint32_t aoff = ((lm0 + lr) * XP + k0 + lc) * 2;
                ldm_x4(xh_u + aoff, ah[0], ah[1], ah[2], ah[3]);
                ldm_x4(xl_u + aoff, al[0], al[1], al[2], al[3]);
                #pragma unroll
                for (int rr = 0; rr < 2; rr++) {
                    int n0 = nh * 32 + rr * 16;
                    uint32_t bh[4], bl[4];
                    uint32_t boff = ((64 + k0 + lr) * XP + n0 + lc) * 2; // W rows
                    ldm_x4t(xh_u + boff, bh[0], bh[1], bh[2], bh[3]);
                    ldm_x4t(xl_u + boff, bl[0], bl[1], bl[2], bl[3]);
                    mma_bf16(qacc[rr*2],   ah[0],ah[1],ah[2],ah[3], bh[0],bh[1]);
                    mma_bf16(qacc[rr*2],   al[0],al[1],al[2],al[3], bh[0],bh[1]);
                    mma_bf16(qacc[rr*2],   ah[0],ah[1],ah[2],ah[3], bl[0],bl[1]);
                    mma_bf16(qacc[rr*2+1], ah[0],ah[1],ah[2],ah[3], bh[2],bh[3]);
                    mma_bf16(qacc[rr*2+1], al[0],al[1],al[2],al[3], bh[2],bh[3]);
                    mma_bf16(qacc[rr*2+1], ah[0],ah[1],ah[2],ah[3], bl[2],bl[3]);
                }
            }
            // scale and store q as bf16 hi/lo
            #pragma unroll
            for (int q = 0; q < 4; q++) {
                int col = nh * 32 + q * 8 + t * 2;
                uint32_t h, l;
                split2(qacc[q][0] * SCALE, qacc[q][1] * SCALE, h, l);
                *(uint32_t*)(qh_s + (lm0 + g) * XP + col) = h;
                *(uint32_t*)(ql_s + (lm0 + g) * XP + col) = l;
                split2(qacc[q][2] * SCALE, qacc[q][3] * SCALE, h, l);
                *(uint32_t*)(qh_s + (lm0 + g + 8) * XP + col) = h;
                *(uint32_t*)(ql_s + (lm0 + g + 8) * XP + col) = l;
            }
        }
        __syncthreads();

        // ============ Phase B: S[64][512] = q @ x^T, chunks of 128 m ============
        for (int c = 0; c < 4; c++) {
            const float* xc = inp + ((size_t)(b * LL + c * 128) * NJ + j) * DD;
            #pragma unroll
            for (int it = 0; it < 8; it++) {
                int idx = tid + it * THREADS;            // 2048 float4
                int r = idx >> 4, c4 = (idx & 15) * 4;
                float4 v = *(const float4*)(xc + r * (NJ * DD) + c4);
                split_store4(xh_s, xl_s, r * XP + c4, v);
            }
            __syncthreads();

            float sacc[8][4];
            #pragma unroll
            for (int q = 0; q < 8; q++)
                #pragma unroll
                for (int i = 0; i < 4; i++) sacc[q][i] = 0.f;

            #pragma unroll
            for (int ks = 0; ks < 4; ks++) {
                int k0 = ks * 16;
                uint32_t ah[4], al[4];
                uint32_t aoff = ((lm0 + lr) * XP + k0 + lc) * 2;
                ldm_x4(qh_u + aoff, ah[0], ah[1], ah[2], ah[3]);
                ldm_x4(ql_u + aoff, al[0], al[1], al[2], al[3]);
                #pragma unroll
                for (int rr = 0; rr < 4; rr++) {
                    int m0 = nh * 64 + rr * 16;
                    uint32_t bh[4], bl[4];
                    uint32_t boff = ((m0 + lc + (lane & 7)) * XP + k0 + ((lane >> 3) & 1) * 8) * 2;
                    ldm_x4(xh_u + boff, bh[0], bh[1], bh[2], bh[3]);
                    ldm_x4(xl_u + boff, bl[0], bl[1], bl[2], bl[3]);
                    mma_bf16(sacc[rr*2],   ah[0],ah[1],ah[2],ah[3], bh[0],bh[1]);
                    mma_bf16(sacc[rr*2],   al[0],al[1],al[2],al[3], bh[0],bh[1]);
                    mma_bf16(sacc[rr*2],   ah[0],ah[1],ah[2],ah[3], bl[0],bl[1]);
                    mma_bf16(sacc[rr*2+1], ah[0],ah[1],ah[2],ah[3], bh[2],bh[3]);
                    mma_bf16(sacc[rr*2+1], al[0],al[1],al[2],al[3], bh[2],bh[3]);
                    mma_bf16(sacc[rr*2+1], ah[0],ah[1],ah[2],ah[3], bl[2],bl[3]);
                }
            }
            // write S chunk (fp32)
            #pragma unroll
            for (int q = 0; q < 8; q++) {
                int col = c * 128 + nh * 64 + q * 8 + t * 2;
                *(float2*)(sS + (lm0 + g) * SPAD + col) =
                    make_float2(sacc[q][0], sacc[q][1]);
                *(float2*)(sS + (lm0 + g + 8) * SPAD + col) =
                    make_float2(sacc[q][2], sacc[q][3]);
            }
            __syncthreads();
        }

        // ============ Phase C: softmax per row + attn write ============
        {
            #pragma unroll 1
            for (int r = 0; r < 8; r++) {
                const int l = warp * 8 + r;
                float* row = sS + l * SPAD;
                float mx = -1e30f;
                #pragma unroll
                for (int tt = 0; tt < 16; tt++) mx = fmaxf(mx, row[lane + tt * 32]);
                #pragma unroll
                for (int s = 16; s > 0; s >>= 1) mx = fmaxf(mx, __shfl_xor_sync(0xffffffffu, mx, s));
                float sum = 0.f;
                #pragma unroll
                for (int tt = 0; tt < 16; tt++) {
                    float e = __expf(row[lane + tt * 32] - mx);
                    row[lane + tt * 32] = e;
                    sum += e;
                }
                #pragma unroll
                for (int s = 16; s > 0; s >>= 1) sum += __shfl_xor_sync(0xffffffffu, sum, s);
                float inv = 1.f / sum;
                __syncwarp();
                size_t aoff = ((size_t)(((o * NJ + j) * BB + b) * LL + l0g + l)) * LL;
                float* ap = attn_out + aoff;
                #pragma unroll
                for (int tt = 0; tt < 4; tt++) {
                    float4 v = *(float4*)(row + lane * 4 + tt * 128);
                    v.x *= inv; v.y *= inv; v.z *= inv; v.w *= inv;
                    *(float4*)(row + lane * 4 + tt * 128) = v;
                    *(float4*)(ap + lane * 4 + tt * 128)  = v;
                }
            }
        }
        __syncthreads();

        // ============ Phase D: ctx += P @ x, chunks of 128 k ============
        for (int c = 0; c < 4; c++) {
            const float* xc = inp + ((size_t)(b * LL + c * 128) * NJ + j) * DD;
            #pragma unroll
            for (int it = 0; it < 8; it++) {
                int idx = tid + it * THREADS;
                int r = idx >> 4, c4 = (idx & 15) * 4;
                float4 v = *(const float4*)(xc + r * (NJ * DD) + c4);
                split_store4(xh_s, xl_s, r * XP + c4, v);
            }
            __syncthreads();

            #pragma unroll
            for (int ks = 0; ks < 8; ks++) {
                int kg = c * 128 + ks * 16;
                int kl = ks * 16;
                // build A fragments (P) from fp32 smem with hi/lo split
                float2 p00 = *(const float2*)(sS + (lm0 + g)     * SPAD + kg + t * 2);
                float2 p10 = *(const float2*)(sS + (lm0 + g + 8) * SPAD + kg + t * 2);
                float2 p01 = *(const float2*)(sS + (lm0 + g)     * SPAD + kg + 8 + t * 2);
                float2 p11 = *(const float2*)(sS + (lm0 + g + 8) * SPAD + kg + 8 + t * 2);
                uint32_t ah[4], al[4];
                split2(p00.x, p00.y, ah[0], al[0]);
                split2(p10.x, p10.y, ah[1], al[1]);
                split2(p01.x, p01.y, ah[2], al[2]);
                split2(p11.x, p11.y, ah[3], al[3]);
                #pragma unroll
                for (int rr = 0; rr < 2; rr++) {
                    int n0 = nh * 32 + rr * 16;
                    uint32_t bh[4], bl[4];
                    uint32_t boff = ((kl + lr) * XP + n0 + lc) * 2;
                    ldm_x4t(xh_u + boff, bh[0], bh[1], bh[2], bh[3]);
                    ldm_x4t(xl_u + boff, bl[0], bl[1], bl[2], bl[3]);
                    mma_bf16(ctx[rr*2],   ah[0],ah[1],ah[2],ah[3], bh[0],bh[1]);
                    mma_bf16(ctx[rr*2],   al[0],al[1],al[2],al[3], bh[0],bh[1]);
                    mma_bf16(ctx[rr*2],   ah[0],ah[1],ah[2],ah[3], bl[0],bl[1]);
                    mma_bf16(ctx[rr*2+1], ah[0],ah[1],ah[2],ah[3], bh[2],bh[3]);
                    mma_bf16(ctx[rr*2+1], al[0],al[1],al[2],al[3], bh[2],bh[3]);
                    mma_bf16(ctx[rr*2+1], ah[0],ah[1],ah[2],ah[3], bl[2],bl[3]);
                }
            }
            __syncthreads();
        }
    } // j

    // ============ Epilogue: out = mean_j ctx, layout [b,l,o,d] ============
    #pragma unroll
    for (int q = 0; q < 4; q++) {
        int col = nh * 32 + q * 8 + t * 2;
        int r0 = l0g + lm0 + g;
        *(float2*)(out + ((size_t)(b * LL + r0) * NO + o) * DD + col) =
            make_float2(ctx[q][0] * 0.25f, ctx[q][1] * 0.25f);
        *(float2*)(out + ((size_t)(b * LL + r0 + 8) * NO + o) * DD + col) =
            make_float2(ctx[q][2] * 0.25f, ctx[q][3] * 0.25f);
    }
}

extern "C" void kernel_launch(void* const* d_in, const int* in_sizes, int n_in,
                              void* d_out, int out_size) {
    const float* inp = (const float*)d_in[0];   // [16,512,4,64]
    const float* W   = (const float*)d_in[1];   // [4,4,64,64]
    float* out = (float*)d_out;

    static int smem_set = 0;
    if (!smem_set) {
        cudaFuncSetAttribute(convattn_mma_kernel,
                             cudaFuncAttributeMaxDynamicSharedMemorySize, SMEM_BYTES);
        smem_set = 1;
    }
    dim3 grid(LL / LT, BB, NO);   // (8, 16, 4)
    convattn_mma_kernel<<<grid, THREADS, SMEM_BYTES>>>(inp, W, out);
}

// round 5
// speedup vs baseline: 3.0382x; 1.0704x over previous
#include <cuda_runtime.h>
#include <cuda_bf16.h>
#include <stdint.h>
#include <math.h>

// Problem constants
#define BB 16
#define LL 512
#define NJ 4
#define NO 4
#define DD 64
#define SCALE 0.125f

#define LT 32          // l rows per block
#define THREADS 256
#define SPAD 520       // fp32 scores row stride
#define XP 72          // bf16 tile row stride (144B)

#define OUT_ELEMS (BB*LL*NO*DD)   // 2097152; attn follows
#define INP_ELEMS (BB*LL*NJ*DD)   // 2097152
#define W_ELEMS   (NO*NJ*DD*DD)   // 65536

// smem: sS 32x520 fp32 = 66560B; xh/xl 128x72 bf16 = 18432B each;
//       qh/ql 32x72 bf16 = 4608B each.  total = 112640B -> 2 CTAs/SM
#define SMEM_BYTES (LT*SPAD*4 + (128*XP)*2*2 + (LT*XP)*2*2)

// Pre-split bf16 hi/lo copies of inp and W (filled by split_kernel each call)
__device__ __align__(16) __nv_bfloat16 g_xh[INP_ELEMS];
__device__ __align__(16) __nv_bfloat16 g_xl[INP_ELEMS];
__device__ __align__(16) __nv_bfloat16 g_wh[W_ELEMS];
__device__ __align__(16) __nv_bfloat16 g_wl[W_ELEMS];

__device__ __forceinline__ uint32_t s2u(const void* p) {
    return (uint32_t)__cvta_generic_to_shared(p);
}
__device__ __forceinline__ void cpa16(uint32_t s, const void* g) {
    asm volatile("cp.async.ca.shared.global [%0], [%1], 16;" :: "r"(s), "l"(g));
}
__device__ __forceinline__ void cp_commit_wait() {
    asm volatile("cp.async.commit_group;");
    asm volatile("cp.async.wait_group 0;" ::: "memory");
}
__device__ __forceinline__ void ldm_x4(uint32_t a, uint32_t& r0, uint32_t& r1,
                                       uint32_t& r2, uint32_t& r3) {
    asm volatile("ldmatrix.sync.aligned.m8n8.x4.shared.b16 {%0,%1,%2,%3}, [%4];"
                 : "=r"(r0), "=r"(r1), "=r"(r2), "=r"(r3) : "r"(a));
}
__device__ __forceinline__ void ldm_x4t(uint32_t a, uint32_t& r0, uint32_t& r1,
                                        uint32_t& r2, uint32_t& r3) {
    asm volatile("ldmatrix.sync.aligned.m8n8.x4.trans.shared.b16 {%0,%1,%2,%3}, [%4];"
                 : "=r"(r0), "=r"(r1), "=r"(r2), "=r"(r3) : "r"(a));
}
__device__ __forceinline__ void mma_bf16(float* c, uint32_t a0, uint32_t a1,
                                         uint32_t a2, uint32_t a3,
                                         uint32_t b0, uint32_t b1) {
    asm volatile("mma.sync.aligned.m16n8k16.row.col.f32.bf16.bf16.f32 "
                 "{%0,%1,%2,%3},{%4,%5,%6,%7},{%8,%9},{%0,%1,%2,%3};"
                 : "+f"(c[0]), "+f"(c[1]), "+f"(c[2]), "+f"(c[3])
                 : "r"(a0), "r"(a1), "r"(a2), "r"(a3), "r"(b0), "r"(b1));
}
__device__ __forceinline__ uint32_t pack2(float x0, float x1) {
    __nv_bfloat162 v = __floats2bfloat162_rn(x0, x1);
    return *reinterpret_cast<uint32_t*>(&v);
}
__device__ __forceinline__ void split2(float x0, float x1, uint32_t& h, uint32_t& l) {
    float h0 = __bfloat162float(__float2bfloat16_rn(x0));
    float h1 = __bfloat162float(__float2bfloat16_rn(x1));
    h = pack2(x0, x1);
    l = pack2(x0 - h0, x1 - h1);
}
__device__ __forceinline__ void split4_u2(float4 v, uint2& H, uint2& L) {
    float h0 = __bfloat162float(__float2bfloat16_rn(v.x));
    float h1 = __bfloat162float(__float2bfloat16_rn(v.y));
    float h2 = __bfloat162float(__float2bfloat16_rn(v.z));
    float h3 = __bfloat162float(__float2bfloat16_rn(v.w));
    H = make_uint2(pack2(v.x, v.y), pack2(v.z, v.w));
    L = make_uint2(pack2(v.x - h0, v.y - h1), pack2(v.z - h2, v.w - h3));
}

// ======================= prologue: split inp/W into bf16 hi/lo =======================
__global__ void split_kernel(const float* __restrict__ inp, const float* __restrict__ W) {
    int idx = blockIdx.x * blockDim.x + threadIdx.x;
    if (idx < INP_ELEMS / 4) {
        float4 v = ((const float4*)inp)[idx];
        uint2 H, L;
        split4_u2(v, H, L);
        ((uint2*)g_xh)[idx] = H;
        ((uint2*)g_xl)[idx] = L;
    } else {
        int w = idx - INP_ELEMS / 4;
        if (w < W_ELEMS / 4) {
            float4 v = ((const float4*)W)[w];
            uint2 H, L;
            split4_u2(v, H, L);
            ((uint2*)g_wh)[w] = H;
            ((uint2*)g_wl)[w] = L;
        }
    }
}

// ======================= main kernel =======================
__global__ __launch_bounds__(THREADS, 2)
void convattn_mma_kernel(float* __restrict__ out)
{
    extern __shared__ char smem[];
    float* sS = (float*)smem;
    __nv_bfloat16* xh_s = (__nv_bfloat16*)(smem + LT * SPAD * 4);
    __nv_bfloat16* xl_s = xh_s + 128 * XP;
    __nv_bfloat16* qh_s = xl_s + 128 * XP;
    __nv_bfloat16* ql_s = qh_s + LT * XP;
    const uint32_t xh_u = s2u(xh_s), xl_u = s2u(xl_s);
    const uint32_t qh_u = s2u(qh_s), ql_u = s2u(ql_s);

    const int tid  = threadIdx.x;
    const int warp = tid >> 5;
    const int lane = tid & 31;
    const int g = lane >> 2, t = lane & 3;
    const int lr = lane & 15, lc = (lane >> 4) * 8;

    const int l0g = blockIdx.x * LT;   // 16 tiles
    const int b   = blockIdx.y;
    const int o   = blockIdx.z;

    const int mw  = warp & 1;          // m-tile (16 rows) within 32-row l-tile
    const int wq  = warp >> 1;         // 0..3 quarter selector
    const int lm0 = mw * 16;

    float* attn_out = out + OUT_ELEMS;

    // ctx accumulator: warp owns rows lm0..+15, cols wq*16..+15
    float ctx[2][4];
    #pragma unroll
    for (int q = 0; q < 2; q++)
        #pragma unroll
        for (int i = 0; i < 4; i++) ctx[q][i] = 0.f;

    for (int j = 0; j < NJ; ++j) {
        // ============ Phase A: stage xl-tile + W (cp.async); q = xl@W ============
        {
            #pragma unroll
            for (int it = 0; it < 2; it++) {        // 512 ops: xl tile rows 0..31
                int i = tid + it * THREADS;
                int sel = i >> 8, r = (i >> 3) & 31, ck = i & 7;
                const __nv_bfloat16* src = (sel ? g_xl : g_xh)
                    + ((size_t)((b * LL + l0g + r) * NJ + j)) * DD + ck * 8;
                uint32_t dst = (sel ? xl_u : xh_u) + (r * XP + ck * 8) * 2;
                cpa16(dst, src);
            }
            #pragma unroll
            for (int it = 0; it < 4; it++) {        // 1024 ops: W at rows 64..127
                int i = tid + it * THREADS;
                int sel = i >> 9, r = (i >> 3) & 63, ck = i & 7;
                const __nv_bfloat16* src = (sel ? g_wl : g_wh)
                    + ((size_t)((o * NJ + j) * DD + r)) * DD + ck * 8;
                uint32_t dst = (sel ? xl_u : xh_u) + ((64 + r) * XP + ck * 8) * 2;
                cpa16(dst, src);
            }
            cp_commit_wait();
        }
        __syncthreads();
        {
            float qacc[2][4];
            #pragma unroll
            for (int q = 0; q < 2; q++)
                #pragma unroll
                for (int i = 0; i < 4; i++) qacc[q][i] = 0.f;
            #pragma unroll
            for (int ks = 0; ks < 4; ks++) {
                int k0 = ks * 16;
                uint32_t ah[4], al[4];
                uint32_t aoff = ((lm0 + lr) * XP + k0 + lc) * 2;
                ldm_x4(xh_u + aoff, ah[0], ah[1], ah[2], ah[3]);
                ldm_x4(xl_u + aoff, al[0], al[1], al[2], al[3]);
                int n0 = wq * 16;
                uint32_t bh[4], bl[4];
                uint32_t boff = ((64 + k0 + lr) * XP + n0 + lc) * 2;
                ldm_x4t(xh_u + boff, bh[0], bh[1], bh[2], bh[3]);
                ldm_x4t(xl_u + boff, bl[0], bl[1], bl[2], bl[3]);
                mma_bf16(qacc[0], ah[0],ah[1],ah[2],ah[3], bh[0],bh[1]);
                mma_bf16(qacc[0], al[0],al[1],al[2],al[3], bh[0],bh[1]);
                mma_bf16(qacc[0], ah[0],ah[1],ah[2],ah[3], bl[0],bl[1]);
                mma_bf16(qacc[1], ah[0],ah[1],ah[2],ah[3], bh[2],bh[3]);
                mma_bf16(qacc[1], al[0],al[1],al[2],al[3], bh[2],bh[3]);
                mma_bf16(qacc[1], ah[0],ah[1],ah[2],ah[3], bl[2],bl[3]);
            }
            #pragma unroll
            for (int q = 0; q < 2; q++) {
                int col = wq * 16 + q * 8 + t * 2;
                uint32_t h, l;
                split2(qacc[q][0] * SCALE, qacc[q][1] * SCALE, h, l);
                *(uint32_t*)(qh_s + (lm0 + g) * XP + col) = h;
                *(uint32_t*)(ql_s + (lm0 + g) * XP + col) = l;
                split2(qacc[q][2] * SCALE, qacc[q][3] * SCALE, h, l);
                *(uint32_t*)(qh_s + (lm0 + g + 8) * XP + col) = h;
                *(uint32_t*)(ql_s + (lm0 + g + 8) * XP + col) = l;
            }
        }
        __syncthreads();

        // ============ Phase B: S[32][512] = q @ x^T, chunks of 128 m ============
        for (int c = 0; c < 4; c++) {
            #pragma unroll
            for (int it = 0; it < 8; it++) {        // 2048 ops: x chunk rows 0..127
                int i = tid + it * THREADS;
                int sel = i >> 10, r = (i >> 3) & 127, ck = i & 7;
                const __nv_bfloat16* src = (sel ? g_xl : g_xh)
                    + ((size_t)((b * LL + c * 128 + r) * NJ + j)) * DD + ck * 8;
                uint32_t dst = (sel ? xl_u : xh_u) + (r * XP + ck * 8) * 2;
                cpa16(dst, src);
            }
            cp_commit_wait();
            __syncthreads();

            float sacc[4][4];
            #pragma unroll
            for (int q = 0; q < 4; q++)
                #pragma unroll
                for (int i = 0; i < 4; i++) sacc[q][i] = 0.f;

            #pragma unroll
            for (int ks = 0; ks < 4; ks++) {
                int k0 = ks * 16;
                uint32_t ah[4], al[4];
                uint32_t aoff = ((lm0 + lr) * XP + k0 + lc) * 2;
                ldm_x4(qh_u + aoff, ah[0], ah[1], ah[2], ah[3]);
                ldm_x4(ql_u + aoff, al[0], al[1], al[2], al[3]);
                #pragma unroll
                for (int rr = 0; rr < 2; rr++) {
                    int m0 = wq * 32 + rr * 16;
                    uint32_t bh[4], bl[4];
                    uint32_t boff = ((m0 + lc + (lane & 7)) * XP + k0 + ((lane >> 3) & 1) * 8) * 2;
                    ldm_x4(xh_u + boff, bh[0], bh[1], bh[2], bh[3]);
                    ldm_x4(xl_u + boff, bl[0], bl[1], bl[2], bl[3]);
                    mma_bf16(sacc[rr*2],   ah[0],ah[1],ah[2],ah[3], bh[0],bh[1]);
                    mma_bf16(sacc[rr*2],   al[0],al[1],al[2],al[3], bh[0],bh[1]);
                    mma_bf16(sacc[rr*2],   ah[0],ah[1],ah[2],ah[3], bl[0],bl[1]);
                    mma_bf16(sacc[rr*2+1], ah[0],ah[1],ah[2],ah[3], bh[2],bh[3]);
                    mma_bf16(sacc[rr*2+1], al[0],al[1],al[2],al[3], bh[2],bh[3]);
                    mma_bf16(sacc[rr*2+1], ah[0],ah[1],ah[2],ah[3], bl[2],bl[3]);
                }
            }
            #pragma unroll
            for (int q = 0; q < 4; q++) {
                int col = c * 128 + wq * 32 + q * 8 + t * 2;
                *(float2*)(sS + (lm0 + g) * SPAD + col) =
                    make_float2(sacc[q][0], sacc[q][1]);
                *(float2*)(sS + (lm0 + g + 8) * SPAD + col) =
                    make_float2(sacc[q][2], sacc[q][3]);
            }
            __syncthreads();
        }

        // ============ Phase C: softmax per row + attn write ============
        {
            #pragma unroll 1
            for (int r = 0; r < 4; r++) {
                const int l = warp * 4 + r;
                float* row = sS + l * SPAD;
                float mx = -1e30f;
                #pragma unroll
                for (int tt = 0; tt < 16; tt++) mx = fmaxf(mx, row[lane + tt * 32]);
                #pragma unroll
                for (int s = 16; s > 0; s >>= 1) mx = fmaxf(mx, __shfl_xor_sync(0xffffffffu, mx, s));
                float sum = 0.f;
                #pragma unroll
                for (int tt = 0; tt < 16; tt++) {
                    float e = __expf(row[lane + tt * 32] - mx);
                    row[lane + tt * 32] = e;
                    sum += e;
                }
                #pragma unroll
                for (int s = 16; s > 0; s >>= 1) sum += __shfl_xor_sync(0xffffffffu, sum, s);
                float inv = 1.f / sum;
                __syncwarp();
                size_t aoff = ((size_t)(((o * NJ + j) * BB + b) * LL + l0g + l)) * LL;
                float* ap = attn_out + aoff;
                #pragma unroll
                for (int tt = 0; tt < 4; tt++) {
                    float4 v = *(float4*)(row + lane * 4 + tt * 128);
                    v.x *= inv; v.y *= inv; v.z *= inv; v.w *= inv;
                    *(float4*)(row + lane * 4 + tt * 128) = v;
                    *(float4*)(ap + lane * 4 + tt * 128)  = v;
                }
            }
        }
        __syncthreads();

        // ============ Phase D: ctx += P @ x, chunks of 128 k ============
        for (int c = 0; c < 4; c++) {
            #pragma unroll
            for (int it = 0; it < 8; it++) {
                int i = tid + it * THREADS;
                int sel = i >> 10, r = (i >> 3) & 127, ck = i & 7;
                const __nv_bfloat16* src = (sel ? g_xl : g_xh)
                    + ((size_t)((b * LL + c * 128 + r) * NJ + j)) * DD + ck * 8;
                uint32_t dst = (sel ? xl_u : xh_u) + (r * XP + ck * 8) * 2;
                cpa16(dst, src);
            }
            cp_commit_wait();
            __syncthreads();

            #pragma unroll
            for (int ks = 0; ks < 8; ks++) {
                int kg = c * 128 + ks * 16;
                int kl = ks * 16;
                float2 p00 = *(const float2*)(sS + (lm0 + g)     * SPAD + kg + t * 2);
                float2 p10 = *(const float2*)(sS + (lm0 + g + 8) * SPAD + kg + t * 2);
                float2 p01 = *(const float2*)(sS + (lm0 + g)     * SPAD + kg + 8 + t * 2);
                float2 p11 = *(const float2*)(sS + (lm0 + g + 8) * SPAD + kg + 8 + t * 2);
                uint32_t ah[4], al[4];
                split2(p00.x, p00.y, ah[0], al[0]);
                split2(p10.x, p10.y, ah[1], al[1]);
                split2(p01.x, p01.y, ah[2], al[2]);
                split2(p11.x, p11.y, ah[3], al[3]);
                int n0 = wq * 16;
                uint32_t bh[4], bl[4];
                uint32_t boff = ((kl + lr) * XP + n0 + lc) * 2;
                ldm_x4t(xh_u + boff, bh[0], bh[1], bh[2], bh[3]);
                ldm_x4t(xl_u + boff, bl[0], bl[1], bl[2], bl[3]);
                mma_bf16(ctx[0], ah[0],ah[1],ah[2],ah[3], bh[0],bh[1]);
                mma_bf16(ctx[0], al[0],al[1],al[2],al[3], bh[0],bh[1]);
                mma_bf16(ctx[0], ah[0],ah[1],ah[2],ah[3], bl[0],bl[1]);
                mma_bf16(ctx[1], ah[0],ah[1],ah[2],ah[3], bh[2],bh[3]);
                mma_bf16(ctx[1], al[0],al[1],al[2],al[3], bh[2],bh[3]);
                mma_bf16(ctx[1], ah[0],ah[1],ah[2],ah[3], bl[2],bl[3]);
            }
            __syncthreads();
        }
    } // j

    // ============ Epilogue: out = mean_j ctx, layout [b,l,o,d] ============
    #pragma unroll
    for (int q = 0; q < 2; q++) {
        int col = wq * 16 + q * 8 + t * 2;
        int r0 = l0g + lm0 + g;
        *(float2*)(out + ((size_t)(b * LL + r0) * NO + o) * DD + col) =
            make_float2(ctx[q][0] * 0.25f, ctx[q][1] * 0.25f);
        *(float2*)(out + ((size_t)(b * LL + r0 + 8) * NO + o) * DD + col) =
            make_float2(ctx[q][2] * 0.25f, ctx[q][3] * 0.25f);
    }
}

extern "C" void kernel_launch(void* const* d_in, const int* in_sizes, int n_in,
                              void* d_out, int out_size) {
    const float* inp = (const float*)d_in[0];   // [16,512,4,64]
    const float* W   = (const float*)d_in[1];   // [4,4,64,64]
    float* out = (float*)d_out;

    static int smem_set = 0;
    if (!smem_set) {
        cudaFuncSetAttribute(convattn_mma_kernel,
                             cudaFuncAttributeMaxDynamicSharedMemorySize, SMEM_BYTES);
        smem_set = 1;
    }

    int total4 = INP_ELEMS / 4 + W_ELEMS / 4;           // 540672
    split_kernel<<<(total4 + THREADS - 1) / THREADS, THREADS>>>(inp, W);

    dim3 grid(LL / LT, BB, NO);   // (16, 16, 4)
    convattn_mma_kernel<<<grid, THREADS, SMEM_BYTES>>>(out);
}